// round 15
// baseline (speedup 1.0000x reference)
#include <cuda_runtime.h>
#include <cuda_fp16.h>
#include <cstdint>

#define B 4
#define T 2048
#define H 1024
#define NH 16
#define DH 64
#define BH (B*NH)
#define QT128 (T/128)     // 16 q-tiles of 128

// ---------------- mma.sync helpers (baseline ISA) ----------------
__device__ __forceinline__ uint32_t smem_u32(const void* p) {
    uint32_t a;
    asm("{ .reg .u64 t; cvta.to.shared.u64 t, %1; cvt.u32.u64 %0, t; }" : "=r"(a) : "l"(p));
    return a;
}
__device__ __forceinline__ void ldsm_x4(uint32_t& r0, uint32_t& r1, uint32_t& r2,
                                        uint32_t& r3, uint32_t addr) {
    asm volatile("ldmatrix.sync.aligned.m8n8.x4.shared.b16 {%0,%1,%2,%3}, [%4];"
                 : "=r"(r0), "=r"(r1), "=r"(r2), "=r"(r3) : "r"(addr));
}
__device__ __forceinline__ void ldsm_x4_t(uint32_t& r0, uint32_t& r1, uint32_t& r2,
                                          uint32_t& r3, uint32_t addr) {
    asm volatile("ldmatrix.sync.aligned.m8n8.x4.trans.shared.b16 {%0,%1,%2,%3}, [%4];"
                 : "=r"(r0), "=r"(r1), "=r"(r2), "=r"(r3) : "r"(addr));
}
__device__ __forceinline__ void mma_f16(float* d, const uint32_t* a, const uint32_t* b) {
    asm volatile("mma.sync.aligned.m16n8k16.row.col.f32.f16.f16.f32 "
        "{%0,%1,%2,%3}, {%4,%5,%6,%7}, {%8,%9}, {%0,%1,%2,%3};"
        : "+f"(d[0]), "+f"(d[1]), "+f"(d[2]), "+f"(d[3])
        : "r"(a[0]), "r"(a[1]), "r"(a[2]), "r"(a[3]), "r"(b[0]), "r"(b[1]));
}
__device__ __forceinline__ void cp16(uint32_t saddr, const void* g) {
    asm volatile("cp.async.cg.shared.global [%0], [%1], 16;" :: "r"(saddr), "l"(g));
}
#define CP_COMMIT() asm volatile("cp.async.commit_group;" ::: "memory")
#define CP_WAIT0()  asm volatile("cp.async.wait_group 0;" ::: "memory")
#define CP_WAIT1()  asm volatile("cp.async.wait_group 1;" ::: "memory")

// packed fp16 exp2
__device__ __forceinline__ uint32_t ex2_h2(uint32_t x) {
    uint32_t y; asm("ex2.approx.f16x2 %0, %1;" : "=r"(y) : "r"(x)); return y;
}
__device__ __forceinline__ uint32_t pack_h2(float a, float b) {
    __half2 h = __floats2half2_rn(a, b);
    return *(uint32_t*)&h;
}

// swizzled byte offset of 16B chunk c (0..7) in row r of a 128B-row tile
__device__ __forceinline__ uint32_t swz_off(int r, int c) {
    return (uint32_t)(r * 128 + ((c ^ (r & 7)) << 4));
}

// ---------------- scratch ----------------
__device__ float Psum[BH * QT128 * DH];
__device__ __half Xh[(size_t)B * T * H];      // x fp16
__device__ __half Whg[3 * H * H];             // W fp16
__device__ __half QhG[(size_t)BH * T * DH];   // Q fp16, pre-scaled by 0.125*log2(e)
__device__ __half KhG[(size_t)BH * T * DH];   // K fp16
__device__ __half VhG[(size_t)BH * T * DH];   // V fp16

// ---------------------------------------------------------------------------
// Merged convert kernel (unchanged)
// ---------------------------------------------------------------------------
__global__ __launch_bounds__(256) void convert_all_kernel(
    const float* __restrict__ x, const float* __restrict__ Wq,
    const float* __restrict__ Wk, const float* __restrict__ Wv)
{
    const int gb = blockIdx.x;
    const float* __restrict__ src;
    __half* __restrict__ dst;
    size_t base;
    if (gb < 2048) {
        base = (size_t)gb * 4096;
        src = x; dst = Xh;
    } else {
        int wb = gb - 2048;
        int which = wb >> 8;
        base = (size_t)(wb & 255) * 4096;
        src = (which == 0) ? Wq : (which == 1) ? Wk : Wv;
        dst = Whg + (size_t)which * H * H;
    }
    const int t = threadIdx.x;
    #pragma unroll
    for (int j = 0; j < 4; j++) {
        size_t idx = base + (size_t)(t + 256 * j) * 4;
        float4 v = *(const float4*)(src + idx);
        __half hs[4] = { __float2half_rn(v.x), __float2half_rn(v.y),
                         __float2half_rn(v.z), __float2half_rn(v.w) };
        *(uint2*)(dst + idx) = *(uint2*)hs;
    }
}

// ---------------------------------------------------------------------------
// Kernel 1: FUSED QKV projection, 128m x 64n per CTA, 2 CTAs/SM.
// grid = (64, 16), 256 threads, 8 warps (4m x 2n), warp tile 32m x 32n.
// Stage = A(16KB) + 3 x B(8KB) = 40KB, 2 stages = 80KB.
// ---------------------------------------------------------------------------
#define BKP 64
#define NSTG (H / BKP)
#define PA_OFF 0
#define PB_OFF 16384            // B[w] at PB_OFF + w*8192
#define PSTAGE_B 40960          // 40KB per stage
#define PROJ_SMEM (2 * PSTAGE_B + 1024)

__global__ __launch_bounds__(256, 2) void proj_mma_kernel()
{
    extern __shared__ char dsm[];
    char* smp = (char*)(((uintptr_t)dsm + 1023) & ~(uintptr_t)1023);
    const uint32_t sb = smem_u32(smp);

    const int m0 = blockIdx.x * 128;
    const int n0 = blockIdx.y * 64;          // one head per CTA (n0 = head*64)
    const int tid = threadIdx.x;
    const int lane = tid & 31;
    const int wid = tid >> 5;
    const int wm = wid & 3;                  // 4 m-groups of 32 rows
    const int wn = wid >> 2;                 // 2 n-groups of 32 cols

    const char* __restrict__ XhB = (const char*)Xh;
    const char* __restrict__ W0 = (const char*)(Whg);
    const char* __restrict__ W1 = (const char*)(Whg + (size_t)H * H);
    const char* __restrict__ W2 = (const char*)(Whg + (size_t)2 * H * H);

    float acc[3][2][4][4];
    #pragma unroll
    for (int w = 0; w < 3; w++)
        #pragma unroll
        for (int i = 0; i < 2; i++)
            #pragma unroll
            for (int j = 0; j < 4; j++)
                #pragma unroll
                for (int q = 0; q < 4; q++) acc[w][i][j][q] = 0.f;

    auto issue_stage = [&](int i) {
        const int k0 = i * BKP;
        const uint32_t st = sb + (i & 1) * PSTAGE_B;
        // A: 128 rows x 128B = 1024 chunks
        #pragma unroll
        for (int it = 0; it < 4; it++) {
            int idx = tid + 256 * it;
            int r = idx >> 3, c = idx & 7;
            uint32_t so = swz_off(r, c);
            size_t ga = ((size_t)(m0 + r) * H + k0) * 2 + c * 16;
            cp16(st + PA_OFF + so, XhB + ga);
        }
        // B[w]: 64 rows x 128B = 512 chunks each
        #pragma unroll
        for (int it = 0; it < 2; it++) {
            int idx = tid + 256 * it;
            int r = idx >> 3, c = idx & 7;
            uint32_t so = swz_off(r, c);
            size_t gb = ((size_t)(n0 + r) * H + k0) * 2 + c * 16;
            cp16(st + PB_OFF + 0 * 8192 + so, W0 + gb);
            cp16(st + PB_OFF + 1 * 8192 + so, W1 + gb);
            cp16(st + PB_OFF + 2 * 8192 + so, W2 + gb);
        }
        CP_COMMIT();
    };

    issue_stage(0);

    for (int i = 0; i < NSTG; i++) {
        CP_WAIT0();
        __syncthreads();
        if (i + 1 < NSTG) issue_stage(i + 1);

        const uint32_t st = sb + (i & 1) * PSTAGE_B;

        #pragma unroll
        for (int k16 = 0; k16 < 4; k16++) {
            uint32_t ah[2][4];
            #pragma unroll
            for (int mt = 0; mt < 2; mt++) {
                int row = wm * 32 + mt * 16 + (lane & 15);
                int chunk = k16 * 2 + (lane >> 4);
                uint32_t so = swz_off(row, chunk);
                ldsm_x4(ah[mt][0], ah[mt][1], ah[mt][2], ah[mt][3], st + PA_OFF + so);
            }
            int mat = lane >> 3, rin = lane & 7;
            #pragma unroll
            for (int w = 0; w < 3; w++) {
                #pragma unroll
                for (int nt = 0; nt < 2; nt++) {
                    int nrow = wn * 32 + nt * 16 + (mat >> 1) * 8 + rin;
                    int chunk = k16 * 2 + (mat & 1);
                    uint32_t so = swz_off(nrow, chunk);
                    uint32_t b0, b1, b2, b3;
                    ldsm_x4(b0, b1, b2, b3, st + PB_OFF + w * 8192 + so);
                    uint32_t bf[2][2] = { {b0, b1}, {b2, b3} };
                    #pragma unroll
                    for (int mt = 0; mt < 2; mt++) {
                        #pragma unroll
                        for (int j = 0; j < 2; j++)
                            mma_f16(acc[w][mt][nt * 2 + j], ah[mt], bf[j]);
                    }
                }
            }
        }
    }

    // Epilogue: fp16 head-split stores. n0 = head*64 -> h0 = blockIdx.y.
    const int h0 = blockIdx.y;
    #pragma unroll
    for (int w = 0; w < 3; w++) {
        __half* __restrict__ Og = (w == 0) ? QhG : (w == 1) ? KhG : VhG;
        const float scale = (w == 0) ? 0.18033688011112042f : 1.0f;
        #pragma unroll
        for (int mt = 0; mt < 2; mt++) {
            int row0 = m0 + wm * 32 + mt * 16 + (lane >> 2);
            #pragma unroll
            for (int nf = 0; nf < 4; nf++) {
                int d0 = wn * 32 + nf * 8 + 2 * (lane & 3);
                #pragma unroll
                for (int half = 0; half < 2; half++) {
                    int m = row0 + half * 8;
                    int b = m >> 11, t = m & 2047;
                    __half2 hv = __floats2half2_rn(acc[w][mt][nf][half*2]   * scale,
                                                   acc[w][mt][nf][half*2+1] * scale);
                    size_t off = ((size_t)(b * NH + h0) * T + t) * DH + d0;
                    *(__half2*)(Og + off) = hv;
                }
            }
        }
    }
}

// ---------------------------------------------------------------------------
// Kernel 2: flash attention (unchanged from R14)
// ---------------------------------------------------------------------------
#define AT_K 0
#define AT_V 16384
#define AT_STAGE 32768
#define ATT_SMEM (3 * AT_STAGE + 1024)

__global__ __launch_bounds__(256) void attn_mma_kernel()
{
    extern __shared__ char dsm[];
    __shared__ float red[8][64];
    char* smp = (char*)(((uintptr_t)dsm + 1023) & ~(uintptr_t)1023);
    const uint32_t sb = smem_u32(smp);

    const int qt = blockIdx.x;
    const int bh = blockIdx.y;
    const int tid = threadIdx.x;
    const int wid = tid >> 5;
    const int lane = tid & 31;
    const int q0 = qt * 128;

    const char* __restrict__ QP = (const char*)(QhG + (size_t)bh * T * DH);
    const char* __restrict__ KP = (const char*)(KhG + (size_t)bh * T * DH);
    const char* __restrict__ VP = (const char*)(VhG + (size_t)bh * T * DH);

    #pragma unroll
    for (int it = 0; it < 4; it++) {
        int idx = tid + 256 * it;
        int r = idx >> 3, c = idx & 7;
        cp16(sb + swz_off(r, c), QP + (size_t)(q0 + r) * 128 + c * 16);
    }
    CP_COMMIT();
    CP_WAIT0();
    __syncthreads();

    uint32_t qh[4][4];
    #pragma unroll
    for (int k16 = 0; k16 < 4; k16++) {
        int row = wid * 16 + (lane & 15);
        int chunk = k16 * 2 + (lane >> 4);
        uint32_t so = swz_off(row, chunk);
        ldsm_x4(qh[k16][0], qh[k16][1], qh[k16][2], qh[k16][3], sb + so);
    }
    __syncthreads();

    auto issue_kv = [&](int i) {
        const int s0 = i * 128;
        const uint32_t st = sb + (i % 3) * AT_STAGE;
        #pragma unroll
        for (int it = 0; it < 8; it++) {
            int idx = tid + 256 * it;
            int r = idx >> 3, c = idx & 7;
            int rr = r & 127;
            uint32_t so = swz_off(rr, c);
            size_t g = (size_t)(s0 + rr) * 128 + c * 16;
            if (r < 128) cp16(st + AT_K + so, KP + g);
            else         cp16(st + AT_V + so, VP + g);
        }
        CP_COMMIT();
    };

    issue_kv(0);
    issue_kv(1);

    const uint32_t ONES2[2] = { 0x3C003C00u, 0x3C003C00u };
    float lacc[4];
    #pragma unroll
    for (int q = 0; q < 4; q++) lacc[q] = 0.f;
    float oacc[8][4];
    #pragma unroll
    for (int t = 0; t < 8; t++)
        #pragma unroll
        for (int q = 0; q < 4; q++) oacc[t][q] = 0.f;

    for (int i = 0; i < 16; i++) {
        if (i < 15) { CP_WAIT1(); } else { CP_WAIT0(); }
        __syncthreads();
        if (i + 2 < 16) issue_kv(i + 2);

        const uint32_t stg = sb + (i % 3) * AT_STAGE;

        #pragma unroll
        for (int hf = 0; hf < 2; hf++) {
            const uint32_t stK = stg + AT_K + hf * 8192;
            const uint32_t stV = stg + AT_V + hf * 8192;

            float sacc[8][4];
            #pragma unroll
            for (int t = 0; t < 8; t++)
                #pragma unroll
                for (int q = 0; q < 4; q++) sacc[t][q] = 0.f;

            #pragma unroll
            for (int k16 = 0; k16 < 4; k16++) {
                #pragma unroll
                for (int nt = 0; nt < 4; nt++) {
                    int mat = lane >> 3, rin = lane & 7;
                    int nrow = nt * 16 + (mat >> 1) * 8 + rin;
                    int chunk = k16 * 2 + (mat & 1);
                    uint32_t so = swz_off(nrow, chunk);
                    uint32_t b0, b1, b2, b3;
                    ldsm_x4(b0, b1, b2, b3, stK + so);
                    uint32_t bf01[2] = {b0, b1}, bf23[2] = {b2, b3};
                    mma_f16(sacc[2*nt],   qh[k16], bf01);
                    mma_f16(sacc[2*nt+1], qh[k16], bf23);
                }
            }

            uint32_t phA[8], phB[8];
            #pragma unroll
            for (int t = 0; t < 8; t++) {
                phA[t] = ex2_h2(pack_h2(sacc[t][0], sacc[t][1]));
                phB[t] = ex2_h2(pack_h2(sacc[t][2], sacc[t][3]));
            }

            #pragma unroll
            for (int j = 0; j < 4; j++) {
                uint32_t Ah[4] = { phA[2*j], phB[2*j], phA[2*j+1], phB[2*j+1] };
                mma_f16(lacc, Ah, ONES2);
                #pragma unroll
                for (int tt = 0; tt < 8; tt += 2) {
                    int mi = lane >> 3;
                    int row = 16*j + (mi & 1) * 8 + (lane & 7);
                    int chunk = tt + (mi >> 1);
                    uint32_t so = swz_off(row, chunk);
                    uint32_t b0, b1, b2, b3;
                    ldsm_x4_t(b0, b1, b2, b3, stV + so);
                    uint32_t bf01[2] = {b0, b1}, bf23[2] = {b2, b3};
                    mma_f16(oacc[tt],   Ah, bf01);
                    mma_f16(oacc[tt+1], Ah, bf23);
                }
            }
        }
    }

    float inv0 = 1.f / lacc[0];
    float inv1 = 1.f / lacc[2];

    float cp0[8], cp1[8];
    #pragma unroll
    for (int t = 0; t < 8; t++) {
        cp0[t] = oacc[t][0] * inv0 + oacc[t][2] * inv1;
        cp1[t] = oacc[t][1] * inv0 + oacc[t][3] * inv1;
    }
    #pragma unroll
    for (int msk = 4; msk < 32; msk <<= 1) {
        #pragma unroll
        for (int t = 0; t < 8; t++) {
            cp0[t] += __shfl_xor_sync(0xffffffffu, cp0[t], msk);
            cp1[t] += __shfl_xor_sync(0xffffffffu, cp1[t], msk);
        }
    }
    if ((lane >> 2) == 0) {
        #pragma unroll
        for (int t = 0; t < 8; t++) {
            red[wid][8*t + 2*lane + 0] = cp0[t];
            red[wid][8*t + 2*lane + 1] = cp1[t];
        }
    }
    __syncthreads();
    if (tid < 64) {
        float s = 0.f;
        #pragma unroll
        for (int w = 0; w < 8; w++) s += red[w][tid];
        Psum[((size_t)bh * QT128 + qt) * DH + tid] = s;
    }
}

// ---------------------------------------------------------------------------
// Kernel 3: merged reduce + output projection.
// grid = 64 blocks: b = blk>>4, n-range = (blk&15)*64. Each block rebuilds
// Mctx[b] (1024 floats) in smem from Psum, then does 64 output dots.
// ---------------------------------------------------------------------------
__global__ __launch_bounds__(256) void out_kernel(
    const float* __restrict__ Wo, const float* __restrict__ bo,
    float* __restrict__ out)
{
    __shared__ float mc[H];
    const int b = blockIdx.x >> 4;
    const int n0 = (blockIdx.x & 15) * 64;
    const int tid = threadIdx.x;
    const int wid = tid >> 5;
    const int lane = tid & 31;

    #pragma unroll
    for (int v = 0; v < 4; v++) {
        int idx = tid + 256 * v;          // 0..1023
        int h = idx >> 6, d = idx & 63;
        int bh = b * NH + h;
        float s = 0.f;
        #pragma unroll
        for (int qt = 0; qt < QT128; qt++)
            s += Psum[((size_t)bh * QT128 + qt) * DH + d];
        mc[idx] = s * (1.0f / T);
    }
    __syncthreads();

    #pragma unroll
    for (int j = 0; j < 8; j++) {
        int n = n0 + wid * 8 + j;
        const float* __restrict__ wrow = Wo + (size_t)n * H;
        float s = 0.f;
        #pragma unroll 4
        for (int k = lane; k < H; k += 32) s += mc[k] * wrow[k];
        #pragma unroll
        for (int d = 16; d; d >>= 1) s += __shfl_xor_sync(0xffffffffu, s, d);
        if (lane == 0) out[b * H + n] = s + bo[n];
    }
}

// ---------------------------------------------------------------------------
extern "C" void kernel_launch(void* const* d_in, const int* in_sizes, int n_in,
                              void* d_out, int out_size)
{
    const float* x  = (const float*)d_in[0];
    const float* Wq = (const float*)d_in[1];
    const float* Wk = (const float*)d_in[2];
    const float* Wv = (const float*)d_in[3];
    const float* Wo = (const float*)d_in[4];
    const float* bo = (const float*)d_in[5];
    float* out = (float*)d_out;

    cudaFuncSetAttribute(proj_mma_kernel,
                         cudaFuncAttributeMaxDynamicSharedMemorySize, PROJ_SMEM);
    cudaFuncSetAttribute(attn_mma_kernel,
                         cudaFuncAttributeMaxDynamicSharedMemorySize, ATT_SMEM);

    convert_all_kernel<<<2816, 256>>>(x, Wq, Wk, Wv);
    proj_mma_kernel<<<dim3(64, 16), 256, PROJ_SMEM>>>();
    attn_mma_kernel<<<dim3(QT128, BH), 256, ATT_SMEM>>>();
    out_kernel<<<64, 256>>>(Wo, bo, out);
}

// round 16
// speedup vs baseline: 1.0567x; 1.0567x over previous
#include <cuda_runtime.h>
#include <cuda_fp16.h>
#include <cstdint>

#define B 4
#define T 2048
#define H 1024
#define NH 16
#define DH 64
#define BH (B*NH)
#define QT128 (T/128)     // 16 q-tiles of 128

// ---------------- mma.sync helpers (baseline ISA) ----------------
__device__ __forceinline__ uint32_t smem_u32(const void* p) {
    uint32_t a;
    asm("{ .reg .u64 t; cvta.to.shared.u64 t, %1; cvt.u32.u64 %0, t; }" : "=r"(a) : "l"(p));
    return a;
}
__device__ __forceinline__ void ldsm_x4(uint32_t& r0, uint32_t& r1, uint32_t& r2,
                                        uint32_t& r3, uint32_t addr) {
    asm volatile("ldmatrix.sync.aligned.m8n8.x4.shared.b16 {%0,%1,%2,%3}, [%4];"
                 : "=r"(r0), "=r"(r1), "=r"(r2), "=r"(r3) : "r"(addr));
}
__device__ __forceinline__ void ldsm_x4_t(uint32_t& r0, uint32_t& r1, uint32_t& r2,
                                          uint32_t& r3, uint32_t addr) {
    asm volatile("ldmatrix.sync.aligned.m8n8.x4.trans.shared.b16 {%0,%1,%2,%3}, [%4];"
                 : "=r"(r0), "=r"(r1), "=r"(r2), "=r"(r3) : "r"(addr));
}
__device__ __forceinline__ void mma_f16(float* d, const uint32_t* a, const uint32_t* b) {
    asm volatile("mma.sync.aligned.m16n8k16.row.col.f32.f16.f16.f32 "
        "{%0,%1,%2,%3}, {%4,%5,%6,%7}, {%8,%9}, {%0,%1,%2,%3};"
        : "+f"(d[0]), "+f"(d[1]), "+f"(d[2]), "+f"(d[3])
        : "r"(a[0]), "r"(a[1]), "r"(a[2]), "r"(a[3]), "r"(b[0]), "r"(b[1]));
}
__device__ __forceinline__ void cp16(uint32_t saddr, const void* g) {
    asm volatile("cp.async.cg.shared.global [%0], [%1], 16;" :: "r"(saddr), "l"(g));
}
#define CP_COMMIT() asm volatile("cp.async.commit_group;" ::: "memory")
#define CP_WAIT0()  asm volatile("cp.async.wait_group 0;" ::: "memory")
#define CP_WAIT1()  asm volatile("cp.async.wait_group 1;" ::: "memory")

// packed fp16 exp2
__device__ __forceinline__ uint32_t ex2_h2(uint32_t x) {
    uint32_t y; asm("ex2.approx.f16x2 %0, %1;" : "=r"(y) : "r"(x)); return y;
}
__device__ __forceinline__ uint32_t pack_h2(float a, float b) {
    __half2 h = __floats2half2_rn(a, b);
    return *(uint32_t*)&h;
}

// swizzled byte offset of 16B chunk c (0..7) in row r of a 128B-row tile
__device__ __forceinline__ uint32_t swz_off(int r, int c) {
    return (uint32_t)(r * 128 + ((c ^ (r & 7)) << 4));
}

// ---------------- scratch ----------------
__device__ float Psum[BH * QT128 * DH];
__device__ float Mctx[B * H];
__device__ __half Xh[(size_t)B * T * H];      // x fp16
__device__ __half Whg[3 * H * H];             // W fp16
__device__ __half QhG[(size_t)BH * T * DH];   // Q fp16, pre-scaled by 0.125*log2(e)
__device__ __half KhG[(size_t)BH * T * DH];   // K fp16
__device__ __half VhG[(size_t)BH * T * DH];   // V fp16

// ---------------------------------------------------------------------------
// Merged convert kernel (unchanged)
// ---------------------------------------------------------------------------
__global__ __launch_bounds__(256) void convert_all_kernel(
    const float* __restrict__ x, const float* __restrict__ Wq,
    const float* __restrict__ Wk, const float* __restrict__ Wv)
{
    const int gb = blockIdx.x;
    const float* __restrict__ src;
    __half* __restrict__ dst;
    size_t base;
    if (gb < 2048) {
        base = (size_t)gb * 4096;
        src = x; dst = Xh;
    } else {
        int wb = gb - 2048;
        int which = wb >> 8;
        base = (size_t)(wb & 255) * 4096;
        src = (which == 0) ? Wq : (which == 1) ? Wk : Wv;
        dst = Whg + (size_t)which * H * H;
    }
    const int t = threadIdx.x;
    #pragma unroll
    for (int j = 0; j < 4; j++) {
        size_t idx = base + (size_t)(t + 256 * j) * 4;
        float4 v = *(const float4*)(src + idx);
        __half hs[4] = { __float2half_rn(v.x), __float2half_rn(v.y),
                         __float2half_rn(v.z), __float2half_rn(v.w) };
        *(uint2*)(dst + idx) = *(uint2*)hs;
    }
}

// ---------------------------------------------------------------------------
// Kernel 1: FUSED QKV projection, 128m x 64n per CTA, 2 CTAs/SM.
// grid = (64, 16), 256 threads, 8 warps (4m x 2n), warp tile 32m x 32n.
// Stage = A(16KB) + 3 x B(8KB) = 40KB, 2 stages = 80KB.  (R15 version, kept)
// ---------------------------------------------------------------------------
#define BKP 64
#define NSTG (H / BKP)
#define PA_OFF 0
#define PB_OFF 16384            // B[w] at PB_OFF + w*8192
#define PSTAGE_B 40960          // 40KB per stage
#define PROJ_SMEM (2 * PSTAGE_B + 1024)

__global__ __launch_bounds__(256, 2) void proj_mma_kernel()
{
    extern __shared__ char dsm[];
    char* smp = (char*)(((uintptr_t)dsm + 1023) & ~(uintptr_t)1023);
    const uint32_t sb = smem_u32(smp);

    const int m0 = blockIdx.x * 128;
    const int n0 = blockIdx.y * 64;          // one head per CTA
    const int tid = threadIdx.x;
    const int lane = tid & 31;
    const int wid = tid >> 5;
    const int wm = wid & 3;
    const int wn = wid >> 2;

    const char* __restrict__ XhB = (const char*)Xh;
    const char* __restrict__ W0 = (const char*)(Whg);
    const char* __restrict__ W1 = (const char*)(Whg + (size_t)H * H);
    const char* __restrict__ W2 = (const char*)(Whg + (size_t)2 * H * H);

    float acc[3][2][4][4];
    #pragma unroll
    for (int w = 0; w < 3; w++)
        #pragma unroll
        for (int i = 0; i < 2; i++)
            #pragma unroll
            for (int j = 0; j < 4; j++)
                #pragma unroll
                for (int q = 0; q < 4; q++) acc[w][i][j][q] = 0.f;

    auto issue_stage = [&](int i) {
        const int k0 = i * BKP;
        const uint32_t st = sb + (i & 1) * PSTAGE_B;
        #pragma unroll
        for (int it = 0; it < 4; it++) {
            int idx = tid + 256 * it;
            int r = idx >> 3, c = idx & 7;
            uint32_t so = swz_off(r, c);
            size_t ga = ((size_t)(m0 + r) * H + k0) * 2 + c * 16;
            cp16(st + PA_OFF + so, XhB + ga);
        }
        #pragma unroll
        for (int it = 0; it < 2; it++) {
            int idx = tid + 256 * it;
            int r = idx >> 3, c = idx & 7;
            uint32_t so = swz_off(r, c);
            size_t gb = ((size_t)(n0 + r) * H + k0) * 2 + c * 16;
            cp16(st + PB_OFF + 0 * 8192 + so, W0 + gb);
            cp16(st + PB_OFF + 1 * 8192 + so, W1 + gb);
            cp16(st + PB_OFF + 2 * 8192 + so, W2 + gb);
        }
        CP_COMMIT();
    };

    issue_stage(0);

    for (int i = 0; i < NSTG; i++) {
        CP_WAIT0();
        __syncthreads();
        if (i + 1 < NSTG) issue_stage(i + 1);

        const uint32_t st = sb + (i & 1) * PSTAGE_B;

        #pragma unroll
        for (int k16 = 0; k16 < 4; k16++) {
            uint32_t ah[2][4];
            #pragma unroll
            for (int mt = 0; mt < 2; mt++) {
                int row = wm * 32 + mt * 16 + (lane & 15);
                int chunk = k16 * 2 + (lane >> 4);
                uint32_t so = swz_off(row, chunk);
                ldsm_x4(ah[mt][0], ah[mt][1], ah[mt][2], ah[mt][3], st + PA_OFF + so);
            }
            int mat = lane >> 3, rin = lane & 7;
            #pragma unroll
            for (int w = 0; w < 3; w++) {
                #pragma unroll
                for (int nt = 0; nt < 2; nt++) {
                    int nrow = wn * 32 + nt * 16 + (mat >> 1) * 8 + rin;
                    int chunk = k16 * 2 + (mat & 1);
                    uint32_t so = swz_off(nrow, chunk);
                    uint32_t b0, b1, b2, b3;
                    ldsm_x4(b0, b1, b2, b3, st + PB_OFF + w * 8192 + so);
                    uint32_t bf[2][2] = { {b0, b1}, {b2, b3} };
                    #pragma unroll
                    for (int mt = 0; mt < 2; mt++) {
                        #pragma unroll
                        for (int j = 0; j < 2; j++)
                            mma_f16(acc[w][mt][nt * 2 + j], ah[mt], bf[j]);
                    }
                }
            }
        }
    }

    const int h0 = blockIdx.y;
    #pragma unroll
    for (int w = 0; w < 3; w++) {
        __half* __restrict__ Og = (w == 0) ? QhG : (w == 1) ? KhG : VhG;
        const float scale = (w == 0) ? 0.18033688011112042f : 1.0f;
        #pragma unroll
        for (int mt = 0; mt < 2; mt++) {
            int row0 = m0 + wm * 32 + mt * 16 + (lane >> 2);
            #pragma unroll
            for (int nf = 0; nf < 4; nf++) {
                int d0 = wn * 32 + nf * 8 + 2 * (lane & 3);
                #pragma unroll
                for (int half = 0; half < 2; half++) {
                    int m = row0 + half * 8;
                    int b = m >> 11, t = m & 2047;
                    __half2 hv = __floats2half2_rn(acc[w][mt][nf][half*2]   * scale,
                                                   acc[w][mt][nf][half*2+1] * scale);
                    size_t off = ((size_t)(b * NH + h0) * T + t) * DH + d0;
                    *(__half2*)(Og + off) = hv;
                }
            }
        }
    }
}

// ---------------------------------------------------------------------------
// Kernel 2: flash attention (unchanged)
// ---------------------------------------------------------------------------
#define AT_K 0
#define AT_V 16384
#define AT_STAGE 32768
#define ATT_SMEM (3 * AT_STAGE + 1024)

__global__ __launch_bounds__(256) void attn_mma_kernel()
{
    extern __shared__ char dsm[];
    __shared__ float red[8][64];
    char* smp = (char*)(((uintptr_t)dsm + 1023) & ~(uintptr_t)1023);
    const uint32_t sb = smem_u32(smp);

    const int qt = blockIdx.x;
    const int bh = blockIdx.y;
    const int tid = threadIdx.x;
    const int wid = tid >> 5;
    const int lane = tid & 31;
    const int q0 = qt * 128;

    const char* __restrict__ QP = (const char*)(QhG + (size_t)bh * T * DH);
    const char* __restrict__ KP = (const char*)(KhG + (size_t)bh * T * DH);
    const char* __restrict__ VP = (const char*)(VhG + (size_t)bh * T * DH);

    #pragma unroll
    for (int it = 0; it < 4; it++) {
        int idx = tid + 256 * it;
        int r = idx >> 3, c = idx & 7;
        cp16(sb + swz_off(r, c), QP + (size_t)(q0 + r) * 128 + c * 16);
    }
    CP_COMMIT();
    CP_WAIT0();
    __syncthreads();

    uint32_t qh[4][4];
    #pragma unroll
    for (int k16 = 0; k16 < 4; k16++) {
        int row = wid * 16 + (lane & 15);
        int chunk = k16 * 2 + (lane >> 4);
        uint32_t so = swz_off(row, chunk);
        ldsm_x4(qh[k16][0], qh[k16][1], qh[k16][2], qh[k16][3], sb + so);
    }
    __syncthreads();

    auto issue_kv = [&](int i) {
        const int s0 = i * 128;
        const uint32_t st = sb + (i % 3) * AT_STAGE;
        #pragma unroll
        for (int it = 0; it < 8; it++) {
            int idx = tid + 256 * it;
            int r = idx >> 3, c = idx & 7;
            int rr = r & 127;
            uint32_t so = swz_off(rr, c);
            size_t g = (size_t)(s0 + rr) * 128 + c * 16;
            if (r < 128) cp16(st + AT_K + so, KP + g);
            else         cp16(st + AT_V + so, VP + g);
        }
        CP_COMMIT();
    };

    issue_kv(0);
    issue_kv(1);

    const uint32_t ONES2[2] = { 0x3C003C00u, 0x3C003C00u };
    float lacc[4];
    #pragma unroll
    for (int q = 0; q < 4; q++) lacc[q] = 0.f;
    float oacc[8][4];
    #pragma unroll
    for (int t = 0; t < 8; t++)
        #pragma unroll
        for (int q = 0; q < 4; q++) oacc[t][q] = 0.f;

    for (int i = 0; i < 16; i++) {
        if (i < 15) { CP_WAIT1(); } else { CP_WAIT0(); }
        __syncthreads();
        if (i + 2 < 16) issue_kv(i + 2);

        const uint32_t stg = sb + (i % 3) * AT_STAGE;

        #pragma unroll
        for (int hf = 0; hf < 2; hf++) {
            const uint32_t stK = stg + AT_K + hf * 8192;
            const uint32_t stV = stg + AT_V + hf * 8192;

            float sacc[8][4];
            #pragma unroll
            for (int t = 0; t < 8; t++)
                #pragma unroll
                for (int q = 0; q < 4; q++) sacc[t][q] = 0.f;

            #pragma unroll
            for (int k16 = 0; k16 < 4; k16++) {
                #pragma unroll
                for (int nt = 0; nt < 4; nt++) {
                    int mat = lane >> 3, rin = lane & 7;
                    int nrow = nt * 16 + (mat >> 1) * 8 + rin;
                    int chunk = k16 * 2 + (mat & 1);
                    uint32_t so = swz_off(nrow, chunk);
                    uint32_t b0, b1, b2, b3;
                    ldsm_x4(b0, b1, b2, b3, stK + so);
                    uint32_t bf01[2] = {b0, b1}, bf23[2] = {b2, b3};
                    mma_f16(sacc[2*nt],   qh[k16], bf01);
                    mma_f16(sacc[2*nt+1], qh[k16], bf23);
                }
            }

            uint32_t phA[8], phB[8];
            #pragma unroll
            for (int t = 0; t < 8; t++) {
                phA[t] = ex2_h2(pack_h2(sacc[t][0], sacc[t][1]));
                phB[t] = ex2_h2(pack_h2(sacc[t][2], sacc[t][3]));
            }

            #pragma unroll
            for (int j = 0; j < 4; j++) {
                uint32_t Ah[4] = { phA[2*j], phB[2*j], phA[2*j+1], phB[2*j+1] };
                mma_f16(lacc, Ah, ONES2);
                #pragma unroll
                for (int tt = 0; tt < 8; tt += 2) {
                    int mi = lane >> 3;
                    int row = 16*j + (mi & 1) * 8 + (lane & 7);
                    int chunk = tt + (mi >> 1);
                    uint32_t so = swz_off(row, chunk);
                    uint32_t b0, b1, b2, b3;
                    ldsm_x4_t(b0, b1, b2, b3, stV + so);
                    uint32_t bf01[2] = {b0, b1}, bf23[2] = {b2, b3};
                    mma_f16(oacc[tt],   Ah, bf01);
                    mma_f16(oacc[tt+1], Ah, bf23);
                }
            }
        }
    }

    float inv0 = 1.f / lacc[0];
    float inv1 = 1.f / lacc[2];

    float cp0[8], cp1[8];
    #pragma unroll
    for (int t = 0; t < 8; t++) {
        cp0[t] = oacc[t][0] * inv0 + oacc[t][2] * inv1;
        cp1[t] = oacc[t][1] * inv0 + oacc[t][3] * inv1;
    }
    #pragma unroll
    for (int msk = 4; msk < 32; msk <<= 1) {
        #pragma unroll
        for (int t = 0; t < 8; t++) {
            cp0[t] += __shfl_xor_sync(0xffffffffu, cp0[t], msk);
            cp1[t] += __shfl_xor_sync(0xffffffffu, cp1[t], msk);
        }
    }
    if ((lane >> 2) == 0) {
        #pragma unroll
        for (int t = 0; t < 8; t++) {
            red[wid][8*t + 2*lane + 0] = cp0[t];
            red[wid][8*t + 2*lane + 1] = cp1[t];
        }
    }
    __syncthreads();
    if (tid < 64) {
        float s = 0.f;
        #pragma unroll
        for (int w = 0; w < 8; w++) s += red[w][tid];
        Psum[((size_t)bh * QT128 + qt) * DH + tid] = s;
    }
}

// ---------------------------------------------------------------------------
// Kernel 3 & 4: separate reduce and output projection (R14 tail, restored)
// ---------------------------------------------------------------------------
__global__ __launch_bounds__(256) void reduce_kernel()
{
    int idx = blockIdx.x * 256 + threadIdx.x;
    int b = idx >> 10;
    int h = (idx >> 6) & 15;
    int d = idx & 63;
    int bh = b * NH + h;
    float s = 0.f;
    #pragma unroll
    for (int qt = 0; qt < QT128; qt++)
        s += Psum[((size_t)bh * QT128 + qt) * DH + d];
    Mctx[idx] = s * (1.0f / T);
}

__global__ __launch_bounds__(256) void out_kernel(
    const float* __restrict__ Wo, const float* __restrict__ bo,
    float* __restrict__ out)
{
    int gw = (blockIdx.x * 256 + threadIdx.x) >> 5;
    int lane = threadIdx.x & 31;
    int b = gw >> 10;
    int n = gw & 1023;
    const float* __restrict__ wrow = Wo + (size_t)n * H;
    const float* __restrict__ mrow = Mctx + b * H;
    float s = 0.f;
    #pragma unroll 4
    for (int k = lane; k < H; k += 32) s += mrow[k] * wrow[k];
    #pragma unroll
    for (int d = 16; d; d >>= 1) s += __shfl_xor_sync(0xffffffffu, s, d);
    if (lane == 0) out[b * H + n] = s + bo[n];
}

// ---------------------------------------------------------------------------
extern "C" void kernel_launch(void* const* d_in, const int* in_sizes, int n_in,
                              void* d_out, int out_size)
{
    const float* x  = (const float*)d_in[0];
    const float* Wq = (const float*)d_in[1];
    const float* Wk = (const float*)d_in[2];
    const float* Wv = (const float*)d_in[3];
    const float* Wo = (const float*)d_in[4];
    const float* bo = (const float*)d_in[5];
    float* out = (float*)d_out;

    cudaFuncSetAttribute(proj_mma_kernel,
                         cudaFuncAttributeMaxDynamicSharedMemorySize, PROJ_SMEM);
    cudaFuncSetAttribute(attn_mma_kernel,
                         cudaFuncAttributeMaxDynamicSharedMemorySize, ATT_SMEM);

    convert_all_kernel<<<2816, 256>>>(x, Wq, Wk, Wv);
    proj_mma_kernel<<<dim3(64, 16), 256, PROJ_SMEM>>>();
    attn_mma_kernel<<<dim3(QT128, BH), 256, ATT_SMEM>>>();
    reduce_kernel<<<16, 256>>>();
    out_kernel<<<512, 256>>>(Wo, bo, out);
}